// round 3
// baseline (speedup 1.0000x reference)
#include <cuda_runtime.h>

#define BB 128
#define TT 2048
#define NI 128
#define NH 128

typedef unsigned long long ull;

// Packed f32x2 ops (Blackwell sm_103a; FFMA2/FADD2 in SASS)
#define FMA_F32X2(d, a, b, c) \
    asm("fma.rn.f32x2 %0, %1, %2, %3;" : "=l"(d) : "l"(a), "l"(b), "l"(c))
#define ADD_F32X2_(d, a, b) \
    asm("add.rn.f32x2 %0, %1, %2;" : "=l"(d) : "l"(a), "l"(b))
#define PACK_F32X2_(out, lo, hi) \
    asm("mov.b64 %0, {%1, %2};" : "=l"(out) : "r"(lo), "r"(hi))

// ======================================================================
// Kernel A: igates = inputs @ W_in^T + (b_in + b_hh)   -> written to out
//   M = 262144, N = 128, K = 128. 64 rows/CTA, 256 threads, 2 CTA/SM.
//   Inner loop: 16 x fma.rn.f32x2 (cols packed in pairs) + 4 packs + 3 LDS.
// ======================================================================
extern __shared__ float g_smem[];

__global__ void __launch_bounds__(256, 2) igates_kernel(
    const float* __restrict__ inp,
    const float* __restrict__ W_in,
    const float* __restrict__ b_in,
    const float* __restrict__ b_hh,
    float* __restrict__ out)
{
    float* Ast = g_smem;            // [128][64]  (k-major, transposed A tile)
    float* Wst = g_smem + 128 * 64; // [128][128] (k-major, transposed W)
    const int tid = threadIdx.x;
    const long m0 = (long)blockIdx.x * 64;

    #pragma unroll
    for (int it = 0; it < 8; it++) {
        int f  = tid + it * 256;
        int r  = f & 63;
        int k4 = f >> 6;
        float4 v = *(const float4*)(inp + (m0 + r) * NI + (long)k4 * 4);
        Ast[(k4 * 4 + 0) * 64 + r] = v.x;
        Ast[(k4 * 4 + 1) * 64 + r] = v.y;
        Ast[(k4 * 4 + 2) * 64 + r] = v.z;
        Ast[(k4 * 4 + 3) * 64 + r] = v.w;
    }
    #pragma unroll
    for (int it = 0; it < 16; it++) {
        int f  = tid + it * 256;
        int j  = f & 127;
        int k4 = f >> 7;
        float4 v = *(const float4*)(W_in + (long)j * NI + (long)k4 * 4);
        Wst[(k4 * 4 + 0) * 128 + j] = v.x;
        Wst[(k4 * 4 + 1) * 128 + j] = v.y;
        Wst[(k4 * 4 + 2) * 128 + j] = v.z;
        Wst[(k4 * 4 + 3) * 128 + j] = v.w;
    }
    __syncthreads();

    const int tx = tid & 15;   // cols tx*8 .. tx*8+7  (4 packed pairs)
    const int ty = tid >> 4;   // rows ty*4 .. ty*4+3

    ull acc2[4][4];
    #pragma unroll
    for (int r = 0; r < 4; r++)
        #pragma unroll
        for (int c = 0; c < 4; c++) acc2[r][c] = 0ULL;

    #pragma unroll 4
    for (int k = 0; k < 128; k++) {
        float4 a = *(const float4*)(Ast + k * 64 + ty * 4);
        // w pairs come packed for free from LDS.128 (adjacent cols)
        ulonglong2 wA = *(const ulonglong2*)(Wst + k * 128 + tx * 8);
        ulonglong2 wB = *(const ulonglong2*)(Wst + k * 128 + tx * 8 + 4);
        ull w2[4] = {wA.x, wA.y, wB.x, wB.y};
        ull a2[4];
        PACK_F32X2_(a2[0], __float_as_uint(a.x), __float_as_uint(a.x));
        PACK_F32X2_(a2[1], __float_as_uint(a.y), __float_as_uint(a.y));
        PACK_F32X2_(a2[2], __float_as_uint(a.z), __float_as_uint(a.z));
        PACK_F32X2_(a2[3], __float_as_uint(a.w), __float_as_uint(a.w));
        #pragma unroll
        for (int r = 0; r < 4; r++)
            #pragma unroll
            for (int c = 0; c < 4; c++)
                FMA_F32X2(acc2[r][c], a2[r], w2[c], acc2[r][c]);
    }

    float bias[8];
    #pragma unroll
    for (int c = 0; c < 8; c++)
        bias[c] = b_in[tx * 8 + c] + b_hh[tx * 8 + c];

    #pragma unroll
    for (int r = 0; r < 4; r++) {
        long row = m0 + ty * 4 + r;
        float o[8];
        #pragma unroll
        for (int c = 0; c < 4; c++) {
            float2 p = *reinterpret_cast<float2*>(&acc2[r][c]);
            o[2 * c]     = p.x + bias[2 * c];
            o[2 * c + 1] = p.y + bias[2 * c + 1];
        }
        *(float4*)(out + row * NH + tx * 8)     = make_float4(o[0], o[1], o[2], o[3]);
        *(float4*)(out + row * NH + tx * 8 + 4) = make_float4(o[4], o[5], o[6], o[7]);
    }
}

// ======================================================================
// Kernel B: recurrence. 128 CTAs (one per batch) x 512 threads.
//   Output j computed by 4 threads (lanes 4j..4j+3 of same warp):
//   thread q owns i in [q*32, q*32+32): 16 packed FMA2 per step,
//   W_hh slice in 32 regs. Intra-warp shfl.xor reduction -> lane q==0
//   does sigmoid + STS + STG. 4 warps/SMSP hides LDS/RAW latency.
// ======================================================================
__global__ void __launch_bounds__(512, 1) rnn_scan_kernel(
    const float* __restrict__ hidden0,
    const float* __restrict__ W_hh,
    float* __restrict__ io)    // [B][T][NH], igates on entry, h on exit
{
    __shared__ __align__(16) float hb[2][NH];
    const int tid = threadIdx.x;
    const int j = tid >> 2;     // output index 0..127
    const int q = tid & 3;      // i-quarter
    const int b = blockIdx.x;

    // W_hh[j][q*32 .. q*32+31] as 16 packed pairs (32 regs)
    ull w2[16];
    {
        const float* wrow = W_hh + (long)j * NH + q * 32;
        #pragma unroll
        for (int i = 0; i < 8; i++) {
            ulonglong2 v = ((const ulonglong2*)wrow)[i];
            w2[2 * i]     = v.x;
            w2[2 * i + 1] = v.y;
        }
    }

    if (tid < NH) hb[0][tid] = hidden0[(long)b * NH + tid];

    float* row = io + (long)b * TT * NH + j;

    // 4-deep ig prefetch, only in q==0 lanes
    float ig0 = 0.f, ig1 = 0.f, ig2 = 0.f, ig3 = 0.f;
    if (q == 0) {
        ig0 = __ldcg(row);
        ig1 = __ldcg(row + 1L * NH);
        ig2 = __ldcg(row + 2L * NH);
        ig3 = __ldcg(row + 3L * NH);
    }
    __syncthreads();
    int cur = 0;

    for (int t = 0; t < TT; t++) {
        float ig_next = 0.f;
        if (q == 0 && t + 4 < TT) ig_next = __ldcg(row + (long)(t + 4) * NH);

        // partial dot over 32 i's: 8 LDS.128 + 16 FMA2, 4 indep chains
        const ulonglong2* h4 = (const ulonglong2*)(&hb[cur][q * 32]);
        ull a0 = 0ULL, a1 = 0ULL, a2 = 0ULL, a3 = 0ULL;
        #pragma unroll
        for (int i = 0; i < 4; i++) {
            ulonglong2 hA = h4[2 * i];
            ulonglong2 hB = h4[2 * i + 1];
            FMA_F32X2(a0, w2[4 * i + 0], hA.x, a0);
            FMA_F32X2(a1, w2[4 * i + 1], hA.y, a1);
            FMA_F32X2(a2, w2[4 * i + 2], hB.x, a2);
            FMA_F32X2(a3, w2[4 * i + 3], hB.y, a3);
        }
        ull s01, s23, s;
        ADD_F32X2_(s01, a0, a1);
        ADD_F32X2_(s23, a2, a3);
        ADD_F32X2_(s, s01, s23);
        float2 sp = *reinterpret_cast<float2*>(&s);
        float p = sp.x + sp.y;

        // reduce across the 4 lanes sharing j (same warp)
        p += __shfl_xor_sync(0xFFFFFFFFu, p, 1);
        p += __shfl_xor_sync(0xFFFFFFFFu, p, 2);

        if (q == 0) {
            float pre = ig0 + p;
            float h = __fdividef(1.0f, 1.0f + __expf(-pre));
            __stcs(row + (long)t * NH, h);   // overwrite igates slot
            hb[cur ^ 1][j] = h;
        }
        __syncthreads();
        cur ^= 1;

        ig0 = ig1; ig1 = ig2; ig2 = ig3; ig3 = ig_next;
    }
}

// ======================================================================
extern "C" void kernel_launch(void* const* d_in, const int* in_sizes, int n_in,
                              void* d_out, int out_size)
{
    const float* inp     = (const float*)d_in[0];  // [B,T,NI]
    const float* hidden0 = (const float*)d_in[1];  // [B,NH]
    const float* W_in    = (const float*)d_in[2];  // [NH,NI]
    const float* b_in    = (const float*)d_in[3];  // [NH]
    const float* W_hh    = (const float*)d_in[4];  // [NH,NH]
    const float* b_hh    = (const float*)d_in[5];  // [NH]
    float* out = (float*)d_out;                    // [B,T,NH]

    cudaFuncSetAttribute(igates_kernel,
                         cudaFuncAttributeMaxDynamicSharedMemorySize, 98304);

    const int n_tiles = (BB * TT) / 64;   // 4096
    igates_kernel<<<n_tiles, 256, 98304>>>(inp, W_in, b_in, b_hh, out);
    rnn_scan_kernel<<<BB, 512>>>(hidden0, W_hh, out);
}

// round 4
// speedup vs baseline: 2.0607x; 2.0607x over previous
#include <cuda_runtime.h>

#define BB 128
#define TT 2048
#define NI 128
#define NH 128

typedef unsigned long long ull;

// Packed f32x2 ops (Blackwell sm_103a; FFMA2 in SASS)
#define FMA_F32X2(d, a, b, c) \
    asm("fma.rn.f32x2 %0, %1, %2, %3;" : "=l"(d) : "l"(a), "l"(b), "l"(c))
#define ADD_F32X2_(d, a, b) \
    asm("add.rn.f32x2 %0, %1, %2;" : "=l"(d) : "l"(a), "l"(b))
#define PACK_DUP_F32X2(out, v) \
    asm("mov.b64 %0, {%1, %1};" : "=l"(out) : "f"(v))

// ======================================================================
// Kernel A: igates = inputs @ W_in^T + (b_in + b_hh)   -> out
//   M = 262144, N = 128, K = 128. 64 rows/CTA, 128 threads, 8x8 micro-tile.
//   Per k per thread: 4 LDS.128 (64B) for 64 FMA -> crossbar no longer
//   binding; FFMA2 issue is (32 FFMA2/thread/k).
// ======================================================================
extern __shared__ float g_smem[];

__global__ void __launch_bounds__(128, 2) igates_kernel(
    const float* __restrict__ inp,
    const float* __restrict__ W_in,
    const float* __restrict__ b_in,
    const float* __restrict__ b_hh,
    float* __restrict__ out)
{
    float* Ast = g_smem;            // [128][64]  k-major transposed A tile (32KB)
    float* Wst = g_smem + 128 * 64; // [128][128] k-major transposed W     (64KB)
    const int tid = threadIdx.x;
    const long m0 = (long)blockIdx.x * 64;

    // Load A tile transposed: Ast[k][r] = inp[(m0+r)*NI + k]
    #pragma unroll
    for (int it = 0; it < 16; it++) {
        int f  = tid + it * 128;        // 0 .. 2047
        int r  = f & 63;
        int k4 = f >> 6;                // 0 .. 31
        float4 v = *(const float4*)(inp + (m0 + r) * NI + (long)k4 * 4);
        Ast[(k4 * 4 + 0) * 64 + r] = v.x;
        Ast[(k4 * 4 + 1) * 64 + r] = v.y;
        Ast[(k4 * 4 + 2) * 64 + r] = v.z;
        Ast[(k4 * 4 + 3) * 64 + r] = v.w;
    }
    // Load W transposed: Wst[k][j] = W_in[j*NI + k]
    #pragma unroll
    for (int it = 0; it < 32; it++) {
        int f  = tid + it * 128;        // 0 .. 4095
        int j  = f & 127;
        int k4 = f >> 7;                // 0 .. 31
        float4 v = *(const float4*)(W_in + (long)j * NI + (long)k4 * 4);
        Wst[(k4 * 4 + 0) * 128 + j] = v.x;
        Wst[(k4 * 4 + 1) * 128 + j] = v.y;
        Wst[(k4 * 4 + 2) * 128 + j] = v.z;
        Wst[(k4 * 4 + 3) * 128 + j] = v.w;
    }
    __syncthreads();

    const int tx = tid & 15;   // cols tx*8 .. tx*8+7 (4 packed pairs)
    const int ty = tid >> 4;   // rows ty*8 .. ty*8+7

    ull acc2[8][4];
    #pragma unroll
    for (int r = 0; r < 8; r++)
        #pragma unroll
        for (int c = 0; c < 4; c++) acc2[r][c] = 0ULL;

    #pragma unroll 4
    for (int k = 0; k < 128; k++) {
        float4 aA = *(const float4*)(Ast + k * 64 + ty * 8);
        float4 aB = *(const float4*)(Ast + k * 64 + ty * 8 + 4);
        ulonglong2 wA = *(const ulonglong2*)(Wst + k * 128 + tx * 8);
        ulonglong2 wB = *(const ulonglong2*)(Wst + k * 128 + tx * 8 + 4);
        ull w2[4] = {wA.x, wA.y, wB.x, wB.y};
        float av[8] = {aA.x, aA.y, aA.z, aA.w, aB.x, aB.y, aB.z, aB.w};
        ull a2[8];
        #pragma unroll
        for (int r = 0; r < 8; r++) PACK_DUP_F32X2(a2[r], av[r]);
        #pragma unroll
        for (int r = 0; r < 8; r++)
            #pragma unroll
            for (int c = 0; c < 4; c++)
                FMA_F32X2(acc2[r][c], a2[r], w2[c], acc2[r][c]);
    }

    float bias[8];
    #pragma unroll
    for (int c = 0; c < 8; c++)
        bias[c] = b_in[tx * 8 + c] + b_hh[tx * 8 + c];

    #pragma unroll
    for (int r = 0; r < 8; r++) {
        long row = m0 + ty * 8 + r;
        float o[8];
        #pragma unroll
        for (int c = 0; c < 4; c++) {
            float2 p = *reinterpret_cast<float2*>(&acc2[r][c]);
            o[2 * c]     = p.x + bias[2 * c];
            o[2 * c + 1] = p.y + bias[2 * c + 1];
        }
        *(float4*)(out + row * NH + tx * 8)     = make_float4(o[0], o[1], o[2], o[3]);
        *(float4*)(out + row * NH + tx * 8 + 4) = make_float4(o[4], o[5], o[6], o[7]);
    }
}

// ======================================================================
// Kernel B: recurrence. 128 CTAs x 128 threads (one thread per output j).
//   - W_hh row j in 64 packed f32x2 regs (loaded once)
//   - per step: 64 FFMA2 in 4 indep chains; h loaded in 4 chunks of
//     8 LDS.128, next chunk prefetched while current chunk's FMAs run
//     (kills the per-load 29-cyc exposed LDS latency seen in R2)
//   - ig prefetched 4 steps deep via __ldcg; h stored with __stcs
// ======================================================================
__global__ void __launch_bounds__(128, 1) rnn_scan_kernel(
    const float* __restrict__ hidden0,
    const float* __restrict__ W_hh,
    float* __restrict__ io)    // [B][T][NH], igates on entry, h on exit
{
    __shared__ __align__(16) float hb[2][NH];
    const int j = threadIdx.x;
    const int b = blockIdx.x;

    // W_hh[j][*] as 64 packed pairs (128 regs)
    ull w2[64];
    {
        const ulonglong2* wrow = (const ulonglong2*)(W_hh + (long)j * NH);
        #pragma unroll
        for (int i = 0; i < 32; i++) {
            ulonglong2 v = wrow[i];
            w2[2 * i]     = v.x;
            w2[2 * i + 1] = v.y;
        }
    }

    hb[0][j] = hidden0[(long)b * NH + j];

    float* row = io + (long)b * TT * NH + j;

    // 4-deep ig prefetch pipeline
    float ig0 = __ldcg(row);
    float ig1 = __ldcg(row + 1L * NH);
    float ig2 = __ldcg(row + 2L * NH);
    float ig3 = __ldcg(row + 3L * NH);

    __syncthreads();
    int cur = 0;

    for (int t = 0; t < TT; t++) {
        float ig_next = (t + 4 < TT) ? __ldcg(row + (long)(t + 4) * NH) : 0.f;

        const ulonglong2* h2 = (const ulonglong2*)(&hb[cur][0]);  // 32 x 16B

        // chunked, double-buffered h loads: 8 LDS.128 per chunk
        ulonglong2 buf[2][8];
        #pragma unroll
        for (int i = 0; i < 8; i++) buf[0][i] = h2[i];

        ull a0 = 0ULL, a1 = 0ULL, a2 = 0ULL, a3 = 0ULL;
        #pragma unroll
        for (int c = 0; c < 4; c++) {
            if (c < 3) {
                #pragma unroll
                for (int i = 0; i < 8; i++)
                    buf[(c + 1) & 1][i] = h2[(c + 1) * 8 + i];
            }
            const ulonglong2* hc = buf[c & 1];
            #pragma unroll
            for (int i = 0; i < 4; i++) {
                FMA_F32X2(a0, w2[c * 16 + 4 * i + 0], hc[2 * i].x,     a0);
                FMA_F32X2(a1, w2[c * 16 + 4 * i + 1], hc[2 * i].y,     a1);
                FMA_F32X2(a2, w2[c * 16 + 4 * i + 2], hc[2 * i + 1].x, a2);
                FMA_F32X2(a3, w2[c * 16 + 4 * i + 3], hc[2 * i + 1].y, a3);
            }
        }
        ull s01, s23, s;
        ADD_F32X2_(s01, a0, a1);
        ADD_F32X2_(s23, a2, a3);
        ADD_F32X2_(s, s01, s23);
        float2 sp = *reinterpret_cast<float2*>(&s);

        float pre = ig0 + (sp.x + sp.y);
        float h = __fdividef(1.0f, 1.0f + __expf(-pre));

        __stcs(row + (long)t * NH, h);   // overwrite igates slot with h
        hb[cur ^ 1][j] = h;
        __syncthreads();
        cur ^= 1;

        ig0 = ig1; ig1 = ig2; ig2 = ig3; ig3 = ig_next;
    }
}

// ======================================================================
extern "C" void kernel_launch(void* const* d_in, const int* in_sizes, int n_in,
                              void* d_out, int out_size)
{
    const float* inp     = (const float*)d_in[0];  // [B,T,NI]
    const float* hidden0 = (const float*)d_in[1];  // [B,NH]
    const float* W_in    = (const float*)d_in[2];  // [NH,NI]
    const float* b_in    = (const float*)d_in[3];  // [NH]
    const float* W_hh    = (const float*)d_in[4];  // [NH,NH]
    const float* b_hh    = (const float*)d_in[5];  // [NH]
    float* out = (float*)d_out;                    // [B,T,NH]

    cudaFuncSetAttribute(igates_kernel,
                         cudaFuncAttributeMaxDynamicSharedMemorySize, 98304);

    const int n_tiles = (BB * TT) / 64;   // 4096
    igates_kernel<<<n_tiles, 128, 98304>>>(inp, W_in, b_in, b_hh, out);
    rnn_scan_kernel<<<BB, 128>>>(hidden0, W_hh, out);
}

// round 5
// speedup vs baseline: 2.8602x; 1.3880x over previous
#include <cuda_runtime.h>

#define BB 128
#define TT 2048
#define NI 128
#define NH 128

typedef unsigned long long ull;

// Packed f32x2 ops (Blackwell sm_103a; FFMA2 in SASS)
#define FMA_F32X2(d, a, b, c) \
    asm("fma.rn.f32x2 %0, %1, %2, %3;" : "=l"(d) : "l"(a), "l"(b), "l"(c))
#define ADD_F32X2_(d, a, b) \
    asm("add.rn.f32x2 %0, %1, %2;" : "=l"(d) : "l"(a), "l"(b))
#define PACK_DUP_F32X2(out, v) \
    asm("mov.b64 %0, {%1, %1};" : "=l"(out) : "f"(v))

// fast sigmoid: 0.5*tanh(0.5x)+0.5  (MUFU.TANH, ~24 cyc serial)
__device__ __forceinline__ float fast_sigmoid(float x) {
    float t;
    asm("tanh.approx.f32 %0, %1;" : "=f"(t) : "f"(x * 0.5f));
    return fmaf(0.5f, t, 0.5f);
}

// ======================================================================
// Kernel A: igates = inputs @ W_in^T + (b_in + b_hh)   -> out
//   M = 262144, N = 128, K = 128. 64 rows/CTA, 128 threads, 8x8 micro-tile.
// ======================================================================
extern __shared__ float g_smem[];

__global__ void __launch_bounds__(128, 2) igates_kernel(
    const float* __restrict__ inp,
    const float* __restrict__ W_in,
    const float* __restrict__ b_in,
    const float* __restrict__ b_hh,
    float* __restrict__ out)
{
    float* Ast = g_smem;            // [128][64]  k-major transposed A tile (32KB)
    float* Wst = g_smem + 128 * 64; // [128][128] k-major transposed W     (64KB)
    const int tid = threadIdx.x;
    const long m0 = (long)blockIdx.x * 64;

    #pragma unroll
    for (int it = 0; it < 16; it++) {
        int f  = tid + it * 128;
        int r  = f & 63;
        int k4 = f >> 6;
        float4 v = *(const float4*)(inp + (m0 + r) * NI + (long)k4 * 4);
        Ast[(k4 * 4 + 0) * 64 + r] = v.x;
        Ast[(k4 * 4 + 1) * 64 + r] = v.y;
        Ast[(k4 * 4 + 2) * 64 + r] = v.z;
        Ast[(k4 * 4 + 3) * 64 + r] = v.w;
    }
    #pragma unroll
    for (int it = 0; it < 32; it++) {
        int f  = tid + it * 128;
        int j  = f & 127;
        int k4 = f >> 7;
        float4 v = *(const float4*)(W_in + (long)j * NI + (long)k4 * 4);
        Wst[(k4 * 4 + 0) * 128 + j] = v.x;
        Wst[(k4 * 4 + 1) * 128 + j] = v.y;
        Wst[(k4 * 4 + 2) * 128 + j] = v.z;
        Wst[(k4 * 4 + 3) * 128 + j] = v.w;
    }
    __syncthreads();

    const int tx = tid & 15;   // cols tx*8 .. tx*8+7 (4 packed pairs)
    const int ty = tid >> 4;   // rows ty*8 .. ty*8+7

    ull acc2[8][4];
    #pragma unroll
    for (int r = 0; r < 8; r++)
        #pragma unroll
        for (int c = 0; c < 4; c++) acc2[r][c] = 0ULL;

    #pragma unroll 4
    for (int k = 0; k < 128; k++) {
        float4 aA = *(const float4*)(Ast + k * 64 + ty * 8);
        float4 aB = *(const float4*)(Ast + k * 64 + ty * 8 + 4);
        ulonglong2 wA = *(const ulonglong2*)(Wst + k * 128 + tx * 8);
        ulonglong2 wB = *(const ulonglong2*)(Wst + k * 128 + tx * 8 + 4);
        ull w2[4] = {wA.x, wA.y, wB.x, wB.y};
        float av[8] = {aA.x, aA.y, aA.z, aA.w, aB.x, aB.y, aB.z, aB.w};
        ull a2[8];
        #pragma unroll
        for (int r = 0; r < 8; r++) PACK_DUP_F32X2(a2[r], av[r]);
        #pragma unroll
        for (int r = 0; r < 8; r++)
            #pragma unroll
            for (int c = 0; c < 4; c++)
                FMA_F32X2(acc2[r][c], a2[r], w2[c], acc2[r][c]);
    }

    float bias[8];
    #pragma unroll
    for (int c = 0; c < 8; c++)
        bias[c] = b_in[tx * 8 + c] + b_hh[tx * 8 + c];

    #pragma unroll
    for (int r = 0; r < 8; r++) {
        long row = m0 + ty * 8 + r;
        float o[8];
        #pragma unroll
        for (int c = 0; c < 4; c++) {
            float2 p = *reinterpret_cast<float2*>(&acc2[r][c]);
            o[2 * c]     = p.x + bias[2 * c];
            o[2 * c + 1] = p.y + bias[2 * c + 1];
        }
        *(float4*)(out + row * NH + tx * 8)     = make_float4(o[0], o[1], o[2], o[3]);
        *(float4*)(out + row * NH + tx * 8 + 4) = make_float4(o[4], o[5], o[6], o[7]);
    }
}

// ======================================================================
// Kernel B: recurrence. 128 CTAs x 128 threads (thread j = output j).
//   - W_hh row j: 64 packed f32x2 regs
//   - per step: two flat 64-float chunks; each chunk = 8 batched LDS.128
//     (static indices -> ptxas front-batches; one ~29cyc exposure/chunk)
//     followed by 32 FFMA2 in 4 independent chains
//   - sigmoid via MUFU.TANH (saves ~35 cyc/step of serial latency)
//   - ig prefetched 4 steps deep (__ldcg); h stored with __stcs
// ======================================================================
__global__ void __launch_bounds__(128, 1) rnn_scan_kernel(
    const float* __restrict__ hidden0,
    const float* __restrict__ W_hh,
    float* __restrict__ io)    // [B][T][NH], igates on entry, h on exit
{
    __shared__ __align__(16) float hb[2][NH];
    const int j = threadIdx.x;
    const int b = blockIdx.x;

    // W_hh[j][*] as 64 packed pairs (128 regs)
    ull w2[64];
    {
        const ulonglong2* wrow = (const ulonglong2*)(W_hh + (long)j * NH);
        #pragma unroll
        for (int i = 0; i < 32; i++) {
            ulonglong2 v = wrow[i];
            w2[2 * i]     = v.x;
            w2[2 * i + 1] = v.y;
        }
    }

    hb[0][j] = hidden0[(long)b * NH + j];

    float* row = io + (long)b * TT * NH + j;

    float ig0 = __ldcg(row);
    float ig1 = __ldcg(row + 1L * NH);
    float ig2 = __ldcg(row + 2L * NH);
    float ig3 = __ldcg(row + 3L * NH);

    __syncthreads();
    int cur = 0;

    for (int t = 0; t < TT; t++) {
        float ig_next = (t + 4 < TT) ? __ldcg(row + (long)(t + 4) * NH) : 0.f;

        const ulonglong2* h2 = (const ulonglong2*)(&hb[cur][0]);  // 32 x 16B

        ull a0 = 0ULL, a1 = 0ULL, a2 = 0ULL, a3 = 0ULL;

        // ---- chunk 0: h[0..63], 8 batched LDS.128 then 32 FFMA2 ----
        {
            ulonglong2 c0 = h2[0], c1 = h2[1], c2 = h2[2], c3 = h2[3];
            ulonglong2 c4 = h2[4], c5 = h2[5], c6 = h2[6], c7 = h2[7];
            FMA_F32X2(a0, w2[ 0], c0.x, a0); FMA_F32X2(a1, w2[ 1], c0.y, a1);
            FMA_F32X2(a2, w2[ 2], c1.x, a2); FMA_F32X2(a3, w2[ 3], c1.y, a3);
            FMA_F32X2(a0, w2[ 4], c2.x, a0); FMA_F32X2(a1, w2[ 5], c2.y, a1);
            FMA_F32X2(a2, w2[ 6], c3.x, a2); FMA_F32X2(a3, w2[ 7], c3.y, a3);
            FMA_F32X2(a0, w2[ 8], c4.x, a0); FMA_F32X2(a1, w2[ 9], c4.y, a1);
            FMA_F32X2(a2, w2[10], c5.x, a2); FMA_F32X2(a3, w2[11], c5.y, a3);
            FMA_F32X2(a0, w2[12], c6.x, a0); FMA_F32X2(a1, w2[13], c6.y, a1);
            FMA_F32X2(a2, w2[14], c7.x, a2); FMA_F32X2(a3, w2[15], c7.y, a3);
        }
        // ---- chunk 1: h[64..127] ----
        {
            ulonglong2 c0 = h2[ 8], c1 = h2[ 9], c2 = h2[10], c3 = h2[11];
            ulonglong2 c4 = h2[12], c5 = h2[13], c6 = h2[14], c7 = h2[15];
            FMA_F32X2(a0, w2[16], c0.x, a0); FMA_F32X2(a1, w2[17], c0.y, a1);
            FMA_F32X2(a2, w2[18], c1.x, a2); FMA_F32X2(a3, w2[19], c1.y, a3);
            FMA_F32X2(a0, w2[20], c2.x, a0); FMA_F32X2(a1, w2[21], c2.y, a1);
            FMA_F32X2(a2, w2[22], c3.x, a2); FMA_F32X2(a3, w2[23], c3.y, a3);
            FMA_F32X2(a0, w2[24], c4.x, a0); FMA_F32X2(a1, w2[25], c4.y, a1);
            FMA_F32X2(a2, w2[26], c5.x, a2); FMA_F32X2(a3, w2[27], c5.y, a3);
            FMA_F32X2(a0, w2[28], c6.x, a0); FMA_F32X2(a1, w2[29], c6.y, a1);
            FMA_F32X2(a2, w2[30], c7.x, a2); FMA_F32X2(a3, w2[31], c7.y, a3);
        }
        // ---- chunk 2: mapped onto same regs (w2[32..63]) ----
        // NOTE: h only has 16 ulonglong2 (128 floats) -> chunks 0,1 covered
        // all of h with w2[0..31]. w2[32..63] pair with the SAME h values? No:
        // w2 index i pairs with h pair i. 64 pairs total, h2 has 16 entries of
        // 2 pairs each = 32 pairs... (see below, loop completes remaining 32)
        {
            ulonglong2 c0 = h2[0], c1 = h2[1], c2 = h2[2], c3 = h2[3];
            ulonglong2 c4 = h2[4], c5 = h2[5], c6 = h2[6], c7 = h2[7];
            // w2[32+k] multiplies h pair (32+k) -> h floats 64..127 live in
            // h2[8..15]; this block is WRONG pairing. Dead code guard:
            (void)c0; (void)c1; (void)c2; (void)c3;
            (void)c4; (void)c5; (void)c6; (void)c7;
        }
        // Remaining pairs 32..63 (h floats 64..127 were chunk1's data but
        // paired with w2[16..31]; pairs 32..63 need h2[8..15] re-used with
        // w2[32..63]? No -- total pairs = 64 (128 floats / 2). h2[16] entries
        // hold exactly 32 ull pairs. Correct mapping: pair p uses
        // ull p = (p<2? ...) -- handled exhaustively above? pairs 0..31 done.
        // pairs 32..63:
        {
            const ull* hp = (const ull*)(&hb[cur][0]);  // 64 packed pairs
            #pragma unroll
            for (int p = 32; p < 64; p += 4) {
                ull h0 = hp[p], h1 = hp[p + 1], h2v = hp[p + 2], h3 = hp[p + 3];
                FMA_F32X2(a0, w2[p],     h0,  a0);
                FMA_F32X2(a1, w2[p + 1], h1,  a1);
                FMA_F32X2(a2, w2[p + 2], h2v, a2);
                FMA_F32X2(a3, w2[p + 3], h3,  a3);
            }
        }

        ull s01, s23, s;
        ADD_F32X2_(s01, a0, a1);
        ADD_F32X2_(s23, a2, a3);
        ADD_F32X2_(s, s01, s23);
        float2 sp = *reinterpret_cast<float2*>(&s);

        float pre = ig0 + (sp.x + sp.y);
        float h = fast_sigmoid(pre);

        hb[cur ^ 1][j] = h;                 // STS first (gates the barrier)
        __stcs(row + (long)t * NH, h);      // STG fire-and-forget
        __syncthreads();
        cur ^= 1;

        ig0 = ig1; ig1 = ig2; ig2 = ig3; ig3 = ig_next;
    }
}

// ======================================================================
extern "C" void kernel_launch(void* const* d_in, const int* in_sizes, int n_in,
                              void* d_out, int out_size)
{
    const float* inp     = (const float*)d_in[0];  // [B,T,NI]
    const float* hidden0 = (const float*)d_in[1];  // [B,NH]
    const float* W_in    = (const float*)d_in[2];  // [NH,NI]
    const float* b_in    = (const float*)d_in[3];  // [NH]
    const float* W_hh    = (const float*)d_in[4];  // [NH,NH]
    const float* b_hh    = (const float*)d_in[5];  // [NH]
    float* out = (float*)d_out;                    // [B,T,NH]

    cudaFuncSetAttribute(igates_kernel,
                         cudaFuncAttributeMaxDynamicSharedMemorySize, 98304);

    const int n_tiles = (BB * TT) / 64;   // 4096
    igates_kernel<<<n_tiles, 128, 98304>>>(inp, W_in, b_in, b_hh, out);
    rnn_scan_kernel<<<BB, 128>>>(hidden0, W_hh, out);
}

// round 6
// speedup vs baseline: 3.0141x; 1.0538x over previous
#include <cuda_runtime.h>

#define BB 128
#define TT 2048
#define NI 128
#define NH 128

typedef unsigned long long ull;

// Packed f32x2 ops (Blackwell sm_103a; FFMA2 in SASS)
#define FMA_F32X2(d, a, b, c) \
    asm("fma.rn.f32x2 %0, %1, %2, %3;" : "=l"(d) : "l"(a), "l"(b), "l"(c))
#define ADD_F32X2_(d, a, b) \
    asm("add.rn.f32x2 %0, %1, %2;" : "=l"(d) : "l"(a), "l"(b))
#define PACK_DUP_F32X2(out, v) \
    asm("mov.b64 %0, {%1, %1};" : "=l"(out) : "f"(v))

// fast sigmoid: 0.5*tanh(0.5x)+0.5  (MUFU.TANH)
__device__ __forceinline__ float fast_sigmoid(float x) {
    float t;
    asm("tanh.approx.f32 %0, %1;" : "=f"(t) : "f"(x * 0.5f));
    return fmaf(0.5f, t, 0.5f);
}

// ======================================================================
// Kernel A: igates = inputs @ W_in^T + (b_in + b_hh) -> out
//   Persistent-W grid-stride: 296 CTAs x 128 thr, 2 CTA/SM.
//   W tile (64KB) loaded to smem ONCE per CTA; ~14 A-tiles per CTA.
// ======================================================================
extern __shared__ float g_smem[];

__global__ void __launch_bounds__(128, 2) igates_kernel(
    const float* __restrict__ inp,
    const float* __restrict__ W_in,
    const float* __restrict__ b_in,
    const float* __restrict__ b_hh,
    float* __restrict__ out)
{
    float* Ast = g_smem;            // [128][64]  k-major transposed A tile (32KB)
    float* Wst = g_smem + 128 * 64; // [128][128] k-major transposed W     (64KB)
    const int tid = threadIdx.x;

    // Load W transposed once: Wst[k][j] = W_in[j*NI + k]
    #pragma unroll
    for (int it = 0; it < 32; it++) {
        int f  = tid + it * 128;        // 0 .. 4095
        int jj = f & 127;
        int k4 = f >> 7;                // 0 .. 31
        float4 v = *(const float4*)(W_in + (long)jj * NI + (long)k4 * 4);
        Wst[(k4 * 4 + 0) * 128 + jj] = v.x;
        Wst[(k4 * 4 + 1) * 128 + jj] = v.y;
        Wst[(k4 * 4 + 2) * 128 + jj] = v.z;
        Wst[(k4 * 4 + 3) * 128 + jj] = v.w;
    }

    const int tx = tid & 15;   // cols tx*8 .. tx*8+7 (4 packed pairs)
    const int ty = tid >> 4;   // rows ty*8 .. ty*8+7

    float bias[8];
    #pragma unroll
    for (int c = 0; c < 8; c++)
        bias[c] = b_in[tx * 8 + c] + b_hh[tx * 8 + c];

    const int n_tiles = (BB * TT) / 64;   // 4096

    for (int tile = blockIdx.x; tile < n_tiles; tile += gridDim.x) {
        const long m0 = (long)tile * 64;

        __syncthreads();   // previous compute done before overwriting Ast
        // Load A tile transposed: Ast[k][r] = inp[(m0+r)*NI + k]  (streamed)
        #pragma unroll
        for (int it = 0; it < 16; it++) {
            int f  = tid + it * 128;    // 0 .. 2047
            int r  = f & 63;
            int k4 = f >> 6;            // 0 .. 31
            float4 v = __ldcs((const float4*)(inp + (m0 + r) * NI + (long)k4 * 4));
            Ast[(k4 * 4 + 0) * 64 + r] = v.x;
            Ast[(k4 * 4 + 1) * 64 + r] = v.y;
            Ast[(k4 * 4 + 2) * 64 + r] = v.z;
            Ast[(k4 * 4 + 3) * 64 + r] = v.w;
        }
        __syncthreads();

        ull acc2[8][4];
        #pragma unroll
        for (int r = 0; r < 8; r++)
            #pragma unroll
            for (int c = 0; c < 4; c++) acc2[r][c] = 0ULL;

        #pragma unroll 4
        for (int k = 0; k < 128; k++) {
            float4 aA = *(const float4*)(Ast + k * 64 + ty * 8);
            float4 aB = *(const float4*)(Ast + k * 64 + ty * 8 + 4);
            ulonglong2 wA = *(const ulonglong2*)(Wst + k * 128 + tx * 8);
            ulonglong2 wB = *(const ulonglong2*)(Wst + k * 128 + tx * 8 + 4);
            ull w2[4] = {wA.x, wA.y, wB.x, wB.y};
            float av[8] = {aA.x, aA.y, aA.z, aA.w, aB.x, aB.y, aB.z, aB.w};
            ull a2[8];
            #pragma unroll
            for (int r = 0; r < 8; r++) PACK_DUP_F32X2(a2[r], av[r]);
            #pragma unroll
            for (int r = 0; r < 8; r++)
                #pragma unroll
                for (int c = 0; c < 4; c++)
                    FMA_F32X2(acc2[r][c], a2[r], w2[c], acc2[r][c]);
        }

        #pragma unroll
        for (int r = 0; r < 8; r++) {
            long row = m0 + ty * 8 + r;
            float o[8];
            #pragma unroll
            for (int c = 0; c < 4; c++) {
                float2 p = *reinterpret_cast<float2*>(&acc2[r][c]);
                o[2 * c]     = p.x + bias[2 * c];
                o[2 * c + 1] = p.y + bias[2 * c + 1];
            }
            *(float4*)(out + row * NH + tx * 8)     = make_float4(o[0], o[1], o[2], o[3]);
            *(float4*)(out + row * NH + tx * 8 + 4) = make_float4(o[4], o[5], o[6], o[7]);
        }
    }
}

// ======================================================================
// Kernel B: recurrence. 128 CTAs x 128 threads (thread j = output j).
//   Per step: 4 chunks x 8 LDS.128 ping-pong (p/q named regs) —
//   chunk c+1 loads issue before chunk c's 16 FFMA2 -> one exposed
//   LDS latency per step. 64 FFMA2 total, 4 accumulator chains.
//   Time loop unrolled x2 (static double-buffer toggle).
// ======================================================================

// 16 FFMA2 of one 32-float chunk (8 ulonglong2 C0..C7) against W[0..15]
#define FMA_CHUNK(C0,C1,C2,C3,C4,C5,C6,C7, W)                               \
    FMA_F32X2(a0, (W)[ 0], C0.x, a0); FMA_F32X2(a1, (W)[ 1], C0.y, a1);     \
    FMA_F32X2(a2, (W)[ 2], C1.x, a2); FMA_F32X2(a3, (W)[ 3], C1.y, a3);     \
    FMA_F32X2(a0, (W)[ 4], C2.x, a0); FMA_F32X2(a1, (W)[ 5], C2.y, a1);     \
    FMA_F32X2(a2, (W)[ 6], C3.x, a2); FMA_F32X2(a3, (W)[ 7], C3.y, a3);     \
    FMA_F32X2(a0, (W)[ 8], C4.x, a0); FMA_F32X2(a1, (W)[ 9], C4.y, a1);     \
    FMA_F32X2(a2, (W)[10], C5.x, a2); FMA_F32X2(a3, (W)[11], C5.y, a3);     \
    FMA_F32X2(a0, (W)[12], C6.x, a0); FMA_F32X2(a1, (W)[13], C6.y, a1);     \
    FMA_F32X2(a2, (W)[14], C7.x, a2); FMA_F32X2(a3, (W)[15], C7.y, a3);

// One scan step: read HSRC (128 floats), write HDST[j] and gmem row[T]
#define SCAN_STEP(HSRC, HDST, T)                                             \
{                                                                            \
    float ig_next = ((T) + 4 < TT) ? __ldcg(row + (long)((T) + 4) * NH) : 0.f;\
    const ulonglong2* h2 = (const ulonglong2*)(HSRC);                        \
    ull a0 = 0ULL, a1 = 0ULL, a2 = 0ULL, a3 = 0ULL;                          \
    ulonglong2 p0 = h2[0], p1 = h2[1], p2 = h2[2], p3 = h2[3];               \
    ulonglong2 p4 = h2[4], p5 = h2[5], p6 = h2[6], p7 = h2[7];               \
    ulonglong2 q0 = h2[ 8], q1 = h2[ 9], q2 = h2[10], q3 = h2[11];           \
    ulonglong2 q4 = h2[12], q5 = h2[13], q6 = h2[14], q7 = h2[15];           \
    FMA_CHUNK(p0,p1,p2,p3,p4,p5,p6,p7, w2 + 0)                               \
    p0 = h2[16]; p1 = h2[17]; p2 = h2[18]; p3 = h2[19];                      \
    p4 = h2[20]; p5 = h2[21]; p6 = h2[22]; p7 = h2[23];                      \
    FMA_CHUNK(q0,q1,q2,q3,q4,q5,q6,q7, w2 + 16)                              \
    q0 = h2[24]; q1 = h2[25]; q2 = h2[26]; q3 = h2[27];                      \
    q4 = h2[28]; q5 = h2[29]; q6 = h2[30]; q7 = h2[31];                      \
    FMA_CHUNK(p0,p1,p2,p3,p4,p5,p6,p7, w2 + 32)                              \
    FMA_CHUNK(q0,q1,q2,q3,q4,q5,q6,q7, w2 + 48)                              \
    ull s01, s23, s;                                                         \
    ADD_F32X2_(s01, a0, a1);                                                 \
    ADD_F32X2_(s23, a2, a3);                                                 \
    ADD_F32X2_(s, s01, s23);                                                 \
    float2 sp = *reinterpret_cast<float2*>(&s);                              \
    float pre = ig0 + (sp.x + sp.y);                                         \
    float h = fast_sigmoid(pre);                                             \
    (HDST)[j] = h;                                                           \
    __stcs(row + (long)(T) * NH, h);                                         \
    __syncthreads();                                                         \
    ig0 = ig1; ig1 = ig2; ig2 = ig3; ig3 = ig_next;                          \
}

__global__ void __launch_bounds__(128, 1) rnn_scan_kernel(
    const float* __restrict__ hidden0,
    const float* __restrict__ W_hh,
    float* __restrict__ io)    // [B][T][NH], igates on entry, h on exit
{
    __shared__ __align__(16) float hA[NH];
    __shared__ __align__(16) float hB[NH];
    const int j = threadIdx.x;
    const int b = blockIdx.x;

    // W_hh[j][*] as 64 packed pairs (128 regs)
    ull w2[64];
    {
        const ulonglong2* wrow = (const ulonglong2*)(W_hh + (long)j * NH);
        #pragma unroll
        for (int i = 0; i < 32; i++) {
            ulonglong2 v = wrow[i];
            w2[2 * i]     = v.x;
            w2[2 * i + 1] = v.y;
        }
    }

    hA[j] = hidden0[(long)b * NH + j];

    float* row = io + (long)b * TT * NH + j;

    float ig0 = __ldcg(row);
    float ig1 = __ldcg(row + 1L * NH);
    float ig2 = __ldcg(row + 2L * NH);
    float ig3 = __ldcg(row + 3L * NH);

    __syncthreads();

    #pragma unroll 1
    for (int t = 0; t < TT; t += 2) {
        SCAN_STEP(hA, hB, t)
        SCAN_STEP(hB, hA, t + 1)
    }
}

// ======================================================================
extern "C" void kernel_launch(void* const* d_in, const int* in_sizes, int n_in,
                              void* d_out, int out_size)
{
    const float* inp     = (const float*)d_in[0];  // [B,T,NI]
    const float* hidden0 = (const float*)d_in[1];  // [B,NH]
    const float* W_in    = (const float*)d_in[2];  // [NH,NI]
    const float* b_in    = (const float*)d_in[3];  // [NH]
    const float* W_hh    = (const float*)d_in[4];  // [NH,NH]
    const float* b_hh    = (const float*)d_in[5];  // [NH]
    float* out = (float*)d_out;                    // [B,T,NH]

    cudaFuncSetAttribute(igates_kernel,
                         cudaFuncAttributeMaxDynamicSharedMemorySize, 98304);

    igates_kernel<<<296, 128, 98304>>>(inp, W_in, b_in, b_hh, out);
    rnn_scan_kernel<<<BB, 128>>>(hidden0, W_hh, out);
}

// round 7
// speedup vs baseline: 3.9932x; 1.3249x over previous
#include <cuda_runtime.h>

#define BB 128
#define TT 2048
#define NI 128
#define NH 128
#define TILE_T 64
#define N_TILES (TT / TILE_T)   // 32

typedef unsigned long long ull;

// Packed f32x2 ops (Blackwell sm_103a; FFMA2 in SASS)
#define FMA_F32X2(d, a, b, c) \
    asm("fma.rn.f32x2 %0, %1, %2, %3;" : "=l"(d) : "l"(a), "l"(b), "l"(c))
#define ADD_F32X2_(d, a, b) \
    asm("add.rn.f32x2 %0, %1, %2;" : "=l"(d) : "l"(a), "l"(b))
#define PACK_DUP_F32X2(out, v) \
    asm("mov.b64 %0, {%1, %1};" : "=l"(out) : "f"(v))

#define BAR_PROD() asm volatile("bar.sync 1, 128;" ::: "memory")
#define BAR_CONS() asm volatile("bar.sync 2, 128;" ::: "memory")

// fast sigmoid: 0.5*tanh(0.5x)+0.5  (MUFU.TANH)
__device__ __forceinline__ float fast_sigmoid(float x) {
    float t;
    asm("tanh.approx.f32 %0, %1;" : "=f"(t) : "f"(x * 0.5f));
    return fmaf(0.5f, t, 0.5f);
}

// 16 FFMA2 of one 32-float chunk (8 ulonglong2 C0..C7) against W[0..15]
#define FMA_CHUNK(C0,C1,C2,C3,C4,C5,C6,C7, W)                               \
    FMA_F32X2(a0, (W)[ 0], C0.x, a0); FMA_F32X2(a1, (W)[ 1], C0.y, a1);     \
    FMA_F32X2(a2, (W)[ 2], C1.x, a2); FMA_F32X2(a3, (W)[ 3], C1.y, a3);     \
    FMA_F32X2(a0, (W)[ 4], C2.x, a0); FMA_F32X2(a1, (W)[ 5], C2.y, a1);     \
    FMA_F32X2(a2, (W)[ 6], C3.x, a2); FMA_F32X2(a3, (W)[ 7], C3.y, a3);     \
    FMA_F32X2(a0, (W)[ 8], C4.x, a0); FMA_F32X2(a1, (W)[ 9], C4.y, a1);     \
    FMA_F32X2(a2, (W)[10], C5.x, a2); FMA_F32X2(a3, (W)[11], C5.y, a3);     \
    FMA_F32X2(a0, (W)[12], C6.x, a0); FMA_F32X2(a1, (W)[13], C6.y, a1);     \
    FMA_F32X2(a2, (W)[14], C7.x, a2); FMA_F32X2(a3, (W)[15], C7.y, a3);

// One scan step: read HSRC (128 floats), write HDST[j] and gmem row[T]
#define SCAN_STEP(HSRC, HDST, T)                                             \
{                                                                            \
    float ig_next = ((T) + 4 < TT) ? __ldcg(row + (long)((T) + 4) * NH) : 0.f;\
    const ulonglong2* h2 = (const ulonglong2*)(HSRC);                        \
    ull a0 = 0ULL, a1 = 0ULL, a2 = 0ULL, a3 = 0ULL;                          \
    ulonglong2 p0 = h2[0], p1 = h2[1], p2 = h2[2], p3 = h2[3];               \
    ulonglong2 p4 = h2[4], p5 = h2[5], p6 = h2[6], p7 = h2[7];               \
    ulonglong2 q0 = h2[ 8], q1 = h2[ 9], q2 = h2[10], q3 = h2[11];           \
    ulonglong2 q4 = h2[12], q5 = h2[13], q6 = h2[14], q7 = h2[15];           \
    FMA_CHUNK(p0,p1,p2,p3,p4,p5,p6,p7, w2 + 0)                               \
    p0 = h2[16]; p1 = h2[17]; p2 = h2[18]; p3 = h2[19];                      \
    p4 = h2[20]; p5 = h2[21]; p6 = h2[22]; p7 = h2[23];                      \
    FMA_CHUNK(q0,q1,q2,q3,q4,q5,q6,q7, w2 + 16)                              \
    q0 = h2[24]; q1 = h2[25]; q2 = h2[26]; q3 = h2[27];                      \
    q4 = h2[28]; q5 = h2[29]; q6 = h2[30]; q7 = h2[31];                      \
    FMA_CHUNK(p0,p1,p2,p3,p4,p5,p6,p7, w2 + 32)                              \
    FMA_CHUNK(q0,q1,q2,q3,q4,q5,q6,q7, w2 + 48)                              \
    ull s01, s23, s;                                                         \
    ADD_F32X2_(s01, a0, a1);                                                 \
    ADD_F32X2_(s23, a2, a3);                                                 \
    ADD_F32X2_(s, s01, s23);                                                 \
    float2 sp = *reinterpret_cast<float2*>(&s);                              \
    float pre = ig0 + (sp.x + sp.y);                                         \
    float h = fast_sigmoid(pre);                                             \
    (HDST)[j] = h;                                                           \
    __stcs(row + (long)(T) * NH, h);                                         \
    BAR_CONS();                                                              \
    ig0 = ig1; ig1 = ig2; ig2 = ig3; ig3 = ig_next;                          \
}

// ======================================================================
// Fused persistent kernel: 128 CTAs (one per batch) x 256 threads.
//   warps 0-3 (tid 0..127):  PRODUCER — igates tiles, t-ascending.
//   warps 4-7 (tid 128..255): CONSUMER — sequential scan (hi-wid
//   arbiter priority). Handshake: smem flag + __threadfence; producer's
//   __stcg (L2) paired with consumer's __ldcg (L2) -> coherent.
// ======================================================================
extern __shared__ float g_smem[];

__global__ void __launch_bounds__(256, 1) fused_rnn_kernel(
    const float* __restrict__ inp,      // [B,T,NI]
    const float* __restrict__ hidden0,  // [B,NH]
    const float* __restrict__ W_in,     // [NH,NI]
    const float* __restrict__ b_in,     // [NH]
    const float* __restrict__ W_hh,     // [NH,NH]
    const float* __restrict__ b_hh,     // [NH]
    float* __restrict__ out)            // [B,T,NH]
{
    float* Ast = g_smem;                   // [128][64]  32KB (A tile, k-major)
    float* Wst = g_smem + 128 * 64;        // [128][128] 64KB (W_in, k-major)
    float* hA  = g_smem + 128 * 64 + 128 * 128;   // 128 floats
    float* hB  = hA + NH;                          // 128 floats
    volatile int* s_flag = (volatile int*)(hB + NH);

    const int tid = threadIdx.x;
    const int b = blockIdx.x;

    if (tid == 0) *s_flag = 0;
    __syncthreads();   // only full-CTA barrier; before role split

    if (tid < 128) {
        // ============================ PRODUCER ============================
        // Load W_in transposed once: Wst[k][j] = W_in[j*NI + k]
        #pragma unroll
        for (int it = 0; it < 32; it++) {
            int f  = tid + it * 128;        // 0 .. 4095
            int jj = f & 127;
            int k4 = f >> 7;                // 0 .. 31
            float4 v = *(const float4*)(W_in + (long)jj * NI + (long)k4 * 4);
            Wst[(k4 * 4 + 0) * 128 + jj] = v.x;
            Wst[(k4 * 4 + 1) * 128 + jj] = v.y;
            Wst[(k4 * 4 + 2) * 128 + jj] = v.z;
            Wst[(k4 * 4 + 3) * 128 + jj] = v.w;
        }

        const int tx = tid & 15;   // cols tx*8 .. tx*8+7 (4 packed pairs)
        const int ty = tid >> 4;   // rows ty*8 .. ty*8+7

        float bias[8];
        #pragma unroll
        for (int c = 0; c < 8; c++)
            bias[c] = b_in[tx * 8 + c] + b_hh[tx * 8 + c];

        const float* binp = inp + (long)b * TT * NI;
        float*       bout = out + (long)b * TT * NH;

        for (int kt = 0; kt < N_TILES; kt++) {
            const long t0 = (long)kt * TILE_T;

            BAR_PROD();   // previous tile's compute done before Ast overwrite
            // Load A tile transposed: Ast[k][r] = inp[b, t0+r, k] (streamed)
            #pragma unroll
            for (int it = 0; it < 16; it++) {
                int f  = tid + it * 128;    // 0 .. 2047
                int r  = f & 63;
                int k4 = f >> 6;            // 0 .. 31
                float4 v = __ldcs((const float4*)(binp + (t0 + r) * NI + (long)k4 * 4));
                Ast[(k4 * 4 + 0) * 64 + r] = v.x;
                Ast[(k4 * 4 + 1) * 64 + r] = v.y;
                Ast[(k4 * 4 + 2) * 64 + r] = v.z;
                Ast[(k4 * 4 + 3) * 64 + r] = v.w;
            }
            BAR_PROD();

            ull acc2[8][4];
            #pragma unroll
            for (int r = 0; r < 8; r++)
                #pragma unroll
                for (int c = 0; c < 4; c++) acc2[r][c] = 0ULL;

            #pragma unroll 4
            for (int k = 0; k < 128; k++) {
                float4 aA = *(const float4*)(Ast + k * 64 + ty * 8);
                float4 aB = *(const float4*)(Ast + k * 64 + ty * 8 + 4);
                ulonglong2 wA = *(const ulonglong2*)(Wst + k * 128 + tx * 8);
                ulonglong2 wB = *(const ulonglong2*)(Wst + k * 128 + tx * 8 + 4);
                ull w2v[4] = {wA.x, wA.y, wB.x, wB.y};
                float av[8] = {aA.x, aA.y, aA.z, aA.w, aB.x, aB.y, aB.z, aB.w};
                ull a2[8];
                #pragma unroll
                for (int r = 0; r < 8; r++) PACK_DUP_F32X2(a2[r], av[r]);
                #pragma unroll
                for (int r = 0; r < 8; r++)
                    #pragma unroll
                    for (int c = 0; c < 4; c++)
                        FMA_F32X2(acc2[r][c], a2[r], w2v[c], acc2[r][c]);
            }

            #pragma unroll
            for (int r = 0; r < 8; r++) {
                long row_t = t0 + ty * 8 + r;
                float o[8];
                #pragma unroll
                for (int c = 0; c < 4; c++) {
                    float2 p = *reinterpret_cast<float2*>(&acc2[r][c]);
                    o[2 * c]     = p.x + bias[2 * c];
                    o[2 * c + 1] = p.y + bias[2 * c + 1];
                }
                __stcg((float4*)(bout + row_t * NH + tx * 8),
                       make_float4(o[0], o[1], o[2], o[3]));
                __stcg((float4*)(bout + row_t * NH + tx * 8 + 4),
                       make_float4(o[4], o[5], o[6], o[7]));
            }
            __threadfence();   // stores visible (L2) before flag
            BAR_PROD();        // all producer threads fenced
            if (tid == 0) *s_flag = kt + 1;
        }
    } else {
        // ============================ CONSUMER ============================
        const int j = tid - 128;

        // W_hh[j][*] as 64 packed pairs (128 regs)
        ull w2[64];
        {
            const ulonglong2* wrow = (const ulonglong2*)(W_hh + (long)j * NH);
            #pragma unroll
            for (int i = 0; i < 32; i++) {
                ulonglong2 v = wrow[i];
                w2[2 * i]     = v.x;
                w2[2 * i + 1] = v.y;
            }
        }

        hA[j] = hidden0[(long)b * NH + j];

        float* row = out + (long)b * TT * NH + j;

        // wait for tile 0 before the initial ig prefetch
        if (*s_flag < 1) { do { __nanosleep(32); } while (*s_flag < 1); }
        __threadfence_block();

        float ig0 = __ldcg(row);
        float ig1 = __ldcg(row + 1L * NH);
        float ig2 = __ldcg(row + 2L * NH);
        float ig3 = __ldcg(row + 3L * NH);

        BAR_CONS();   // hA visible to all consumer threads

        #pragma unroll 1
        for (int tb = 0; tb < N_TILES; tb++) {
            // block [tb*64, tb*64+63] prefetches ig up to tb*64+67 -> tile tb+1
            int need = tb + 2;
            if (need > N_TILES) need = N_TILES;
            if (*s_flag < need) { do { __nanosleep(32); } while (*s_flag < need); }
            __threadfence_block();

            #pragma unroll 1
            for (int tt = 0; tt < TILE_T; tt += 2) {
                const int t = tb * TILE_T + tt;
                SCAN_STEP(hA, hB, t)
                SCAN_STEP(hB, hA, t + 1)
            }
        }
    }
}

// ======================================================================
extern "C" void kernel_launch(void* const* d_in, const int* in_sizes, int n_in,
                              void* d_out, int out_size)
{
    const float* inp     = (const float*)d_in[0];  // [B,T,NI]
    const float* hidden0 = (const float*)d_in[1];  // [B,NH]
    const float* W_in    = (const float*)d_in[2];  // [NH,NI]
    const float* b_in    = (const float*)d_in[3];  // [NH]
    const float* W_hh    = (const float*)d_in[4];  // [NH,NH]
    const float* b_hh    = (const float*)d_in[5];  // [NH]
    float* out = (float*)d_out;                    // [B,T,NH]

    // smem: Ast 32KB + Wst 64KB + hA/hB 1KB + flag
    const int smem_bytes = (128 * 64 + 128 * 128 + 2 * NH + 16) * 4;
    cudaFuncSetAttribute(fused_rnn_kernel,
                         cudaFuncAttributeMaxDynamicSharedMemorySize, smem_bytes);

    fused_rnn_kernel<<<BB, 256, smem_bytes>>>(inp, hidden0, W_in, b_in,
                                              W_hh, b_hh, out);
}

// round 8
// speedup vs baseline: 4.4581x; 1.1164x over previous
#include <cuda_runtime.h>

#define BB 128
#define TT 2048
#define NI 128
#define NH 128
#define TILE_T 64
#define N_TILES (TT / TILE_T)   // 32
#define RING_SLOTS 128          // 2 tiles of 64 timesteps

typedef unsigned long long ull;

// Packed f32x2 ops (Blackwell sm_103a; FFMA2 in SASS)
#define FMA_F32X2(d, a, b, c) \
    asm("fma.rn.f32x2 %0, %1, %2, %3;" : "=l"(d) : "l"(a), "l"(b), "l"(c))
#define ADD_F32X2_(d, a, b) \
    asm("add.rn.f32x2 %0, %1, %2;" : "=l"(d) : "l"(a), "l"(b))
#define PACK_DUP_F32X2(out, v) \
    asm("mov.b64 %0, {%1, %1};" : "=l"(out) : "f"(v))
#define PACK2_F32X2(out, lo, hi) \
    asm("mov.b64 %0, {%1, %2};" : "=l"(out) : "f"(lo), "f"(hi))

#define BAR_PROD() asm volatile("bar.sync 1, 128;" ::: "memory")
#define BAR_CONS() asm volatile("bar.sync 2, 128;" ::: "memory")

__device__ __forceinline__ int ld_acquire_shared(const int* p) {
    int v;
    asm volatile("ld.acquire.cta.shared.b32 %0, [%1];"
                 : "=r"(v)
                 : "r"((unsigned)__cvta_generic_to_shared(p)) : "memory");
    return v;
}
__device__ __forceinline__ void st_release_shared(int* p, int v) {
    asm volatile("st.release.cta.shared.b32 [%0], %1;"
                 :: "r"((unsigned)__cvta_generic_to_shared(p)), "r"(v)
                 : "memory");
}

// 16 FFMA2 of one 32-float chunk (8 ulonglong2 C0..C7) against W[0..15]
#define FMA_CHUNK(C0,C1,C2,C3,C4,C5,C6,C7, W)                               \
    FMA_F32X2(a0, (W)[ 0], C0.x, a0); FMA_F32X2(a1, (W)[ 1], C0.y, a1);     \
    FMA_F32X2(a2, (W)[ 2], C1.x, a2); FMA_F32X2(a3, (W)[ 3], C1.y, a3);     \
    FMA_F32X2(a0, (W)[ 4], C2.x, a0); FMA_F32X2(a1, (W)[ 5], C2.y, a1);     \
    FMA_F32X2(a2, (W)[ 6], C3.x, a2); FMA_F32X2(a3, (W)[ 7], C3.y, a3);     \
    FMA_F32X2(a0, (W)[ 8], C4.x, a0); FMA_F32X2(a1, (W)[ 9], C4.y, a1);     \
    FMA_F32X2(a2, (W)[10], C5.x, a2); FMA_F32X2(a3, (W)[11], C5.y, a3);     \
    FMA_F32X2(a0, (W)[12], C6.x, a0); FMA_F32X2(a1, (W)[13], C6.y, a1);     \
    FMA_F32X2(a2, (W)[14], C7.x, a2); FMA_F32X2(a3, (W)[15], C7.y, a3);

// One scan step. ig comes from the smem ring (already 0.5*(igate+bias));
// w2 holds 0.5*W_hh. h = 0.5*tanh( ig_h + sum 0.5*w*h ) + 0.5 = sigmoid.
#define SCAN_STEP(HSRC, HDST, T)                                             \
{                                                                            \
    float ig_h = ring[(((T) & (RING_SLOTS - 1)) << 7) + j];                  \
    const ulonglong2* h2 = (const ulonglong2*)(HSRC);                        \
    ull a0 = 0ULL, a1 = 0ULL, a2 = 0ULL, a3 = 0ULL;                          \
    ulonglong2 p0 = h2[0], p1 = h2[1], p2 = h2[2], p3 = h2[3];               \
    ulonglong2 p4 = h2[4], p5 = h2[5], p6 = h2[6], p7 = h2[7];               \
    ulonglong2 q0 = h2[ 8], q1 = h2[ 9], q2 = h2[10], q3 = h2[11];           \
    ulonglong2 q4 = h2[12], q5 = h2[13], q6 = h2[14], q7 = h2[15];           \
    FMA_CHUNK(p0,p1,p2,p3,p4,p5,p6,p7, w2 + 0)                               \
    p0 = h2[16]; p1 = h2[17]; p2 = h2[18]; p3 = h2[19];                      \
    p4 = h2[20]; p5 = h2[21]; p6 = h2[22]; p7 = h2[23];                      \
    FMA_CHUNK(q0,q1,q2,q3,q4,q5,q6,q7, w2 + 16)                              \
    q0 = h2[24]; q1 = h2[25]; q2 = h2[26]; q3 = h2[27];                      \
    q4 = h2[28]; q5 = h2[29]; q6 = h2[30]; q7 = h2[31];                      \
    FMA_CHUNK(p0,p1,p2,p3,p4,p5,p6,p7, w2 + 32)                              \
    FMA_CHUNK(q0,q1,q2,q3,q4,q5,q6,q7, w2 + 48)                              \
    ull s01, s23, s;                                                         \
    ADD_F32X2_(s01, a0, a1);                                                 \
    ADD_F32X2_(s23, a2, a3);                                                 \
    ADD_F32X2_(s, s01, s23);                                                 \
    float2 sp = *reinterpret_cast<float2*>(&s);                              \
    float pre = ig_h + (sp.x + sp.y);                                        \
    float th;                                                                \
    asm("tanh.approx.f32 %0, %1;" : "=f"(th) : "f"(pre));                    \
    float h = fmaf(0.5f, th, 0.5f);                                          \
    (HDST)[j] = h;                                                           \
    __stcs(row + (long)(T) * NH, h);                                         \
    BAR_CONS();                                                              \
}

// ======================================================================
// Fused persistent kernel: 128 CTAs (one per batch) x 256 threads.
//   warps 0-3:  PRODUCER — igates tiles -> smem ring (never to gmem)
//   warps 4-7:  CONSUMER — sequential scan (hi-wid arbiter priority)
//   Flow control: acquire/release smem flags; producer <= 2 tiles ahead.
// ======================================================================
extern __shared__ float g_smem[];

#define WST_OFF   0
#define AST_OFF   (128 * 128)                 // after Wst (64KB)
#define RING_OFF  (AST_OFF + 128 * 64)        // after Ast (32KB)
#define HA_OFF    (RING_OFF + RING_SLOTS * NH)
#define HB_OFF    (HA_OFF + NH)
#define FLAG_OFF  (HB_OFF + NH)
#define SMEM_FLOATS (FLAG_OFF + 8)

__global__ void __launch_bounds__(256, 1) fused_rnn_kernel(
    const float* __restrict__ inp,      // [B,T,NI]
    const float* __restrict__ hidden0,  // [B,NH]
    const float* __restrict__ W_in,     // [NH,NI]
    const float* __restrict__ b_in,     // [NH]
    const float* __restrict__ W_hh,     // [NH,NH]
    const float* __restrict__ b_hh,     // [NH]
    float* __restrict__ out)            // [B,T,NH]
{
    float* Wst  = g_smem + WST_OFF;     // [128][128] k-major W_in
    float* Ast  = g_smem + AST_OFF;     // [128][64]  k-major A tile
    float* ring = g_smem + RING_OFF;    // [128 slots][128] scaled igates
    float* hA   = g_smem + HA_OFF;
    float* hB   = g_smem + HB_OFF;
    int*  flags = (int*)(g_smem + FLAG_OFF);   // [0]=prod tiles, [1]=cons tiles

    const int tid = threadIdx.x;
    const int b = blockIdx.x;

    if (tid == 0) { flags[0] = 0; flags[1] = 0; }
    __syncthreads();   // only full-CTA barrier; before role split

    if (tid < 128) {
        // ============================ PRODUCER ============================
        // Load W_in transposed once: Wst[k][j] = W_in[j*NI + k]
        #pragma unroll
        for (int it = 0; it < 32; it++) {
            int f  = tid + it * 128;
            int jj = f & 127;
            int k4 = f >> 7;
            float4 v = *(const float4*)(W_in + (long)jj * NI + (long)k4 * 4);
            Wst[(k4 * 4 + 0) * 128 + jj] = v.x;
            Wst[(k4 * 4 + 1) * 128 + jj] = v.y;
            Wst[(k4 * 4 + 2) * 128 + jj] = v.z;
            Wst[(k4 * 4 + 3) * 128 + jj] = v.w;
        }

        const int tx = tid & 15;   // cols tx*8 .. tx*8+7 (4 packed pairs)
        const int ty = tid >> 4;   // rows ty*8 .. ty*8+7

        // half-bias: 0.5*(b_in + b_hh)
        float biash[8];
        #pragma unroll
        for (int c = 0; c < 8; c++)
            biash[c] = 0.5f * (b_in[tx * 8 + c] + b_hh[tx * 8 + c]);

        const float* binp = inp + (long)b * TT * NI;

        for (int kt = 0; kt < N_TILES; kt++) {
            const long t0 = (long)kt * TILE_T;

            // ring slot reuse: don't run more than 2 tiles ahead of consumer
            if (kt >= 2) {
                while (ld_acquire_shared(&flags[1]) < kt - 1) __nanosleep(64);
            }

            // Load A tile transposed: Ast[k][r] = inp[b, t0+r, k] (streamed)
            #pragma unroll
            for (int it = 0; it < 16; it++) {
                int f  = tid + it * 128;
                int r  = f & 63;
                int k4 = f >> 6;
                float4 v = __ldcs((const float4*)(binp + (t0 + r) * NI + (long)k4 * 4));
                Ast[(k4 * 4 + 0) * 64 + r] = v.x;
                Ast[(k4 * 4 + 1) * 64 + r] = v.y;
                Ast[(k4 * 4 + 2) * 64 + r] = v.z;
                Ast[(k4 * 4 + 3) * 64 + r] = v.w;
            }
            BAR_PROD();

            ull acc2[8][4];
            #pragma unroll
            for (int r = 0; r < 8; r++)
                #pragma unroll
                for (int c = 0; c < 4; c++) acc2[r][c] = 0ULL;

            #pragma unroll 4
            for (int k = 0; k < 128; k++) {
                float4 aA = *(const float4*)(Ast + k * 64 + ty * 8);
                float4 aB = *(const float4*)(Ast + k * 64 + ty * 8 + 4);
                ulonglong2 wA = *(const ulonglong2*)(Wst + k * 128 + tx * 8);
                ulonglong2 wB = *(const ulonglong2*)(Wst + k * 128 + tx * 8 + 4);
                ull w2v[4] = {wA.x, wA.y, wB.x, wB.y};
                float av[8] = {aA.x, aA.y, aA.z, aA.w, aB.x, aB.y, aB.z, aB.w};
                ull a2[8];
                #pragma unroll
                for (int r = 0; r < 8; r++) PACK_DUP_F32X2(a2[r], av[r]);
                #pragma unroll
                for (int r = 0; r < 8; r++)
                    #pragma unroll
                    for (int c = 0; c < 4; c++)
                        FMA_F32X2(acc2[r][c], a2[r], w2v[c], acc2[r][c]);
            }

            // store 0.5*(acc + bias) into ring slots [(t0+row) mod 128]
            #pragma unroll
            for (int r = 0; r < 8; r++) {
                int slot = (int)((t0 + ty * 8 + r) & (RING_SLOTS - 1));
                float o[8];
                #pragma unroll
                for (int c = 0; c < 4; c++) {
                    float2 p = *reinterpret_cast<float2*>(&acc2[r][c]);
                    o[2 * c]     = fmaf(0.5f, p.x, biash[2 * c]);
                    o[2 * c + 1] = fmaf(0.5f, p.y, biash[2 * c + 1]);
                }
                *(float4*)(ring + slot * NH + tx * 8)     = make_float4(o[0], o[1], o[2], o[3]);
                *(float4*)(ring + slot * NH + tx * 8 + 4) = make_float4(o[4], o[5], o[6], o[7]);
            }
            BAR_PROD();   // all producer STS done (bar drains STS) + Ast reuse safe
            if (tid == 0) st_release_shared(&flags[0], kt + 1);
        }
    } else {
        // ============================ CONSUMER ============================
        const int j = tid - 128;

        // 0.5*W_hh[j][*] as 64 packed pairs (128 regs)
        ull w2[64];
        {
            const float4* wrow = (const float4*)(W_hh + (long)j * NH);
            #pragma unroll
            for (int i = 0; i < 32; i++) {
                float4 v = wrow[i];
                PACK2_F32X2(w2[2 * i],     0.5f * v.x, 0.5f * v.y);
                PACK2_F32X2(w2[2 * i + 1], 0.5f * v.z, 0.5f * v.w);
            }
        }

        hA[j] = hidden0[(long)b * NH + j];

        float* row = out + (long)b * TT * NH + j;

        BAR_CONS();   // hA visible to all consumer threads

        #pragma unroll 1
        for (int tb = 0; tb < N_TILES; tb++) {
            // wait until tile tb's igates are in the ring
            while (ld_acquire_shared(&flags[0]) < tb + 1) __nanosleep(64);

            #pragma unroll 1
            for (int tt = 0; tt < TILE_T; tt += 2) {
                const int t = tb * TILE_T + tt;
                SCAN_STEP(hA, hB, t)
                SCAN_STEP(hB, hA, t + 1)
            }
            if (j == 0) st_release_shared(&flags[1], tb + 1);
        }
    }
}

// ======================================================================
extern "C" void kernel_launch(void* const* d_in, const int* in_sizes, int n_in,
                              void* d_out, int out_size)
{
    const float* inp     = (const float*)d_in[0];  // [B,T,NI]
    const float* hidden0 = (const float*)d_in[1];  // [B,NH]
    const float* W_in    = (const float*)d_in[2];  // [NH,NI]
    const float* b_in    = (const float*)d_in[3];  // [NH]
    const float* W_hh    = (const float*)d_in[4];  // [NH,NH]
    const float* b_hh    = (const float*)d_in[5];  // [NH]
    float* out = (float*)d_out;                    // [B,T,NH]

    const int smem_bytes = SMEM_FLOATS * 4;   // ~165KB
    cudaFuncSetAttribute(fused_rnn_kernel,
                         cudaFuncAttributeMaxDynamicSharedMemorySize, smem_bytes);

    fused_rnn_kernel<<<BB, 256, smem_bytes>>>(inp, hidden0, W_in, b_in,
                                              W_hh, b_hh, out);
}

// round 10
// speedup vs baseline: 4.4973x; 1.0088x over previous
#include <cuda_runtime.h>
#include <cstdint>

#define BB 128
#define TT 2048
#define NI 128
#define NH 128
#define TILE_T 64
#define N_TILES (TT / TILE_T)   // 32
#define RING_SLOTS 128          // 2 tiles

typedef unsigned long long ull;

// ---------------- packed f32x2 (consumer scan) ----------------
#define FMA_F32X2(d, a, b, c) \
    asm("fma.rn.f32x2 %0, %1, %2, %3;" : "=l"(d) : "l"(a), "l"(b), "l"(c))
#define ADD_F32X2_(d, a, b) \
    asm("add.rn.f32x2 %0, %1, %2;" : "=l"(d) : "l"(a), "l"(b))
#define PACK2_F32X2(out, lo, hi) \
    asm("mov.b64 %0, {%1, %2};" : "=l"(out) : "f"(lo), "f"(hi))

#define BAR_PROD() asm volatile("bar.sync 1, 128;" ::: "memory")
#define BAR_CONS() asm volatile("bar.sync 2, 128;" ::: "memory")

__device__ __forceinline__ uint32_t tf32hi(float x) {
    uint32_t u;
    asm("cvt.rna.tf32.f32 %0, %1;" : "=r"(u) : "f"(x));
    return u;
}
__device__ __forceinline__ int ld_acquire_shared(const int* p) {
    int v;
    asm volatile("ld.acquire.cta.shared.b32 %0, [%1];"
                 : "=r"(v) : "r"((unsigned)__cvta_generic_to_shared(p)) : "memory");
    return v;
}
__device__ __forceinline__ void st_release_shared(int* p, int v) {
    asm volatile("st.release.cta.shared.b32 [%0], %1;"
                 :: "r"((unsigned)__cvta_generic_to_shared(p)), "r"(v) : "memory");
}

// tf32 mma m16n8k8 (HMMA; baseline PTX, works on compute_103)
#define MMA_TF32(c0,c1,c2,c3, a0,a1,a2,a3, b0,b1)                            \
    asm volatile("mma.sync.aligned.m16n8k8.row.col.f32.tf32.tf32.f32 "       \
        "{%0,%1,%2,%3}, {%4,%5,%6,%7}, {%8,%9}, {%0,%1,%2,%3};"              \
        : "+f"(c0), "+f"(c1), "+f"(c2), "+f"(c3)                             \
        : "r"(a0), "r"(a1), "r"(a2), "r"(a3), "r"(b0), "r"(b1))

// ---------------- smem layout (float indices) ----------------
#define WHI_F    0                    // W_in hi fragments   (16384 f, 64KB)
#define WLO_F    16384                // W_in lo fragments   (16384 f, 64KB)
#define AF_F     32768                // A tile raw fragments (8192 f, 32KB)
#define RING_F   40960                // ring [128][128]     (16384 f, 64KB)
#define HA_F     57344
#define HB_F     57472
#define FLAGS_F  57600                // [0]=tiles ready, [1]=tiles consumed
#define SMEM_F   57608                // 230432 bytes total

// 16 FFMA2 of one 32-float chunk against W[0..15]
#define FMA_CHUNK(C0,C1,C2,C3,C4,C5,C6,C7, W)                               \
    FMA_F32X2(a0, (W)[ 0], C0.x, a0); FMA_F32X2(a1, (W)[ 1], C0.y, a1);     \
    FMA_F32X2(a2, (W)[ 2], C1.x, a2); FMA_F32X2(a3, (W)[ 3], C1.y, a3);     \
    FMA_F32X2(a0, (W)[ 4], C2.x, a0); FMA_F32X2(a1, (W)[ 5], C2.y, a1);     \
    FMA_F32X2(a2, (W)[ 6], C3.x, a2); FMA_F32X2(a3, (W)[ 7], C3.y, a3);     \
    FMA_F32X2(a0, (W)[ 8], C4.x, a0); FMA_F32X2(a1, (W)[ 9], C4.y, a1);     \
    FMA_F32X2(a2, (W)[10], C5.x, a2); FMA_F32X2(a3, (W)[11], C5.y, a3);     \
    FMA_F32X2(a0, (W)[12], C6.x, a0); FMA_F32X2(a1, (W)[13], C6.y, a1);     \
    FMA_F32X2(a2, (W)[14], C7.x, a2); FMA_F32X2(a3, (W)[15], C7.y, a3);

// One scan step: ig (already 0.5*(igate+bias)) from smem ring
#define SCAN_STEP(HSRC, HDST, T)                                             \
{                                                                            \
    float ig_h = ring[(((T) & (RING_SLOTS - 1)) << 7) + j];                  \
    const ulonglong2* h2 = (const ulonglong2*)(HSRC);                        \
    ull a0 = 0ULL, a1 = 0ULL, a2 = 0ULL, a3 = 0ULL;                          \
    ulonglong2 p0 = h2[0], p1 = h2[1], p2 = h2[2], p3 = h2[3];               \
    ulonglong2 p4 = h2[4], p5 = h2[5], p6 = h2[6], p7 = h2[7];               \
    ulonglong2 q0 = h2[ 8], q1 = h2[ 9], q2 = h2[10], q3 = h2[11];           \
    ulonglong2 q4 = h2[12], q5 = h2[13], q6 = h2[14], q7 = h2[15];           \
    FMA_CHUNK(p0,p1,p2,p3,p4,p5,p6,p7, w2 + 0)                               \
    p0 = h2[16]; p1 = h2[17]; p2 = h2[18]; p3 = h2[19];                      \
    p4 = h2[20]; p5 = h2[21]; p6 = h2[22]; p7 = h2[23];                      \
    FMA_CHUNK(q0,q1,q2,q3,q4,q5,q6,q7, w2 + 16)                              \
    q0 = h2[24]; q1 = h2[25]; q2 = h2[26]; q3 = h2[27];                      \
    q4 = h2[28]; q5 = h2[29]; q6 = h2[30]; q7 = h2[31];                      \
    FMA_CHUNK(p0,p1,p2,p3,p4,p5,p6,p7, w2 + 32)                              \
    FMA_CHUNK(q0,q1,q2,q3,q4,q5,q6,q7, w2 + 48)                              \
    ull s01, s23, s;                                                         \
    ADD_F32X2_(s01, a0, a1);                                                 \
    ADD_F32X2_(s23, a2, a3);                                                 \
    ADD_F32X2_(s, s01, s23);                                                 \
    float2 sp = *reinterpret_cast<float2*>(&s);                              \
    float pre = ig_h + (sp.x + sp.y);                                        \
    float th;                                                                \
    asm("tanh.approx.f32 %0, %1;" : "=f"(th) : "f"(pre));                    \
    float h = fmaf(0.5f, th, 0.5f);                                          \
    (HDST)[j] = h;                                                           \
    __stcs(row + (long)(T) * NH, h);                                         \
    BAR_CONS();                                                              \
}

// ======================================================================
// Fused kernel: 128 CTAs (one per batch) x 256 threads.
//   warps 0-3: PRODUCER — tf32 mma.sync (tensor pipe) -> smem ring
//   warps 4-7: CONSUMER — FFMA2 scan (fma pipe), hi-wid priority
// ======================================================================
extern __shared__ float g_smem[];

__global__ void __launch_bounds__(256, 1) fused_rnn_kernel(
    const float* __restrict__ inp,      // [B,T,NI]
    const float* __restrict__ hidden0,  // [B,NH]
    const float* __restrict__ W_in,     // [NH,NI]
    const float* __restrict__ b_in,     // [NH]
    const float* __restrict__ W_hh,     // [NH,NH]
    const float* __restrict__ b_hh,     // [NH]
    float* __restrict__ out)            // [B,T,NH]
{
    float* Whi  = g_smem + WHI_F;
    float* Wlo  = g_smem + WLO_F;
    float* AF   = g_smem + AF_F;
    float* ring = g_smem + RING_F;
    int*  flags = (int*)(g_smem + FLAGS_F);

    const int tid = threadIdx.x;
    const int wid = tid >> 5;
    const int lane = tid & 31;
    const int b = blockIdx.x;

    if (tid == 0) { flags[0] = 0; flags[1] = 0; }

    // ---- W_in hi/lo fragment prep (all 256 threads, once) ----
    // B-frag for mma.row.col: b0 = W_in[j = nt*8+g, k = ks*8+tg],
    //                         b1 = W_in[j, k+4];  lane = g*4+tg
    // stored at ((nt*16+ks)*32 + lane)*2 + half   (half: 0=b0, 1=b1)
    for (int idx = tid; idx < 128 * 32; idx += 256) {
        int jj = idx >> 5;
        int g4 = idx & 31;
        int k  = g4 * 4;
        float4 v = *(const float4*)(W_in + (long)jj * NI + k);
        float vf[4] = {v.x, v.y, v.z, v.w};
        int nt = jj >> 3, gg = jj & 7, ks = k >> 3;
        int half = (k & 7) >= 4 ? 1 : 0;   // k%8 is 0 or 4
        #pragma unroll
        for (int e = 0; e < 4; e++) {
            uint32_t hu = tf32hi(vf[e]);
            float hf = __uint_as_float(hu);
            uint32_t lu = tf32hi(vf[e] - hf);
            int fa = ((nt * 16 + ks) * 32 + (gg * 4 + e)) * 2 + half;
            Whi[fa] = __uint_as_float(hu);
            Wlo[fa] = __uint_as_float(lu);
        }
    }
    __syncthreads();   // prep done; roles split below

    if (tid < 128) {
        // ============================ PRODUCER ============================
        const float* binp = inp + (long)b * TT * NI;
        const int g  = lane >> 2;   // 0..7
        const int tg = lane & 3;    // 0..3

        // per-thread half-bias pairs: bias[nt] = 0.5*(b_in+b_hh)[nt*8+2tg ..+1]
        float2 biasf[16];
        #pragma unroll
        for (int nt = 0; nt < 16; nt++) {
            int j0 = nt * 8 + tg * 2;
            biasf[nt].x = 0.5f * (b_in[j0]     + b_hh[j0]);
            biasf[nt].y = 0.5f * (b_in[j0 + 1] + b_hh[j0 + 1]);
        }

        for (int kt = 0; kt < N_TILES; kt++) {
            const long t0 = (long)kt * TILE_T;

            // ring space: tiles kt-1,kt occupy the ring
            if (kt >= 2) {
                while (ld_acquire_shared(&flags[1]) < kt - 1) __nanosleep(64);
            }

            // ---- scatter input tile into A-fragment layout ----
            // element (r,k): strip w=r>>4, ks=k>>3, lane=(r&7)*4+(k&3),
            // reg = ((r&15)>=8) + 2*((k&7)>=4);  AF[((w*16+ks)*32+lane)*4+reg]
            #pragma unroll
            for (int it = 0; it < 16; it++) {
                int f = tid + it * 128;          // 0..2047 float4 units
                int r = f >> 5;                  // 0..63
                int g4 = f & 31;
                int k = g4 * 4;
                float4 v = __ldcs((const float4*)(binp + (t0 + r) * NI + k));
                float vf[4] = {v.x, v.y, v.z, v.w};
                int w = r >> 4, ks = k >> 3;
                int reg = (((r & 15) >= 8) ? 1 : 0) + (((k & 7) >= 4) ? 2 : 0);
                int baseaddr = ((w * 16 + ks) * 32 + (r & 7) * 4) * 4 + reg;
                #pragma unroll
                for (int e = 0; e < 4; e++)
                    AF[baseaddr + e * 4] = vf[e];   // lane advances with e
            }
            BAR_PROD();

            // ---- load this warp's A fragments, split hi/lo ----
            uint32_t ah[16][4], al[16][4];
            #pragma unroll
            for (int ks = 0; ks < 16; ks++) {
                float4 v = *(const float4*)(AF + ((wid * 16 + ks) * 32 + lane) * 4);
                float vf[4] = {v.x, v.y, v.z, v.w};
                #pragma unroll
                for (int e = 0; e < 4; e++) {
                    ah[ks][e] = tf32hi(vf[e]);
                    al[ks][e] = tf32hi(vf[e] - __uint_as_float(ah[ks][e]));
                }
            }

            // ---- 16 n-tiles x 16 k-steps x 3 mma ----
            #pragma unroll 1
            for (int nt = 0; nt < 16; nt++) {
                float c0 = 0.f, c1 = 0.f, c2 = 0.f, c3 = 0.f;
                const float2* bhp = (const float2*)(Whi + (nt * 16 * 32) * 2) + lane;
                const float2* blp = (const float2*)(Wlo + (nt * 16 * 32) * 2) + lane;
                #pragma unroll
                for (int ks = 0; ks < 16; ks++) {
                    float2 bh = bhp[ks * 32];
                    float2 bl = blp[ks * 32];
                    uint32_t bh0 = __float_as_uint(bh.x), bh1 = __float_as_uint(bh.y);
                    uint32_t bl0 = __float_as_uint(bl.x), bl1 = __float_as_uint(bl.y);
                    MMA_TF32(c0,c1,c2,c3, ah[ks][0],ah[ks][1],ah[ks][2],ah[ks][3], bh0,bh1);
                    MMA_TF32(c0,c1,c2,c3, al[ks][0],al[ks][1],al[ks][2],al[ks][3], bh0,bh1);
                    MMA_TF32(c0,c1,c2,c3, ah[ks][0],ah[ks][1],ah[ks][2],ah[ks][3], bl0,bl1);
                }
                // ring store: rows t0+w16+g (c0,c1) and +8 (c2,c3), j = nt*8+2tg
                int j0 = nt * 8 + tg * 2;
                int slot0 = (int)((t0 + wid * 16 + g) & (RING_SLOTS - 1));
                int slot1 = (int)((t0 + wid * 16 + g + 8) & (RING_SLOTS - 1));
                *(float2*)(ring + slot0 * NH + j0) =
                    make_float2(fmaf(0.5f, c0, biasf[nt].x), fmaf(0.5f, c1, biasf[nt].y));
                *(float2*)(ring + slot1 * NH + j0) =
                    make_float2(fmaf(0.5f, c2, biasf[nt].x), fmaf(0.5f, c3, biasf[nt].y));
            }
            BAR_PROD();   // all producer warps done storing this tile
            if (tid == 0) st_release_shared(&flags[0], kt + 1);
        }
    } else {
        // ============================ CONSUMER ============================
        const int j = tid - 128;
        float* hA = g_smem + HA_F;
        float* hB = g_smem + HB_F;

        // 0.5*W_hh[j][*] as 64 packed pairs (128 regs)
        ull w2[64];
        {
            const float4* wrow = (const float4*)(W_hh + (long)j * NH);
            #pragma unroll
            for (int i = 0; i < 32; i++) {
                float4 v = wrow[i];
                PACK2_F32X2(w2[2 * i],     0.5f * v.x, 0.5f * v.y);
                PACK2_F32X2(w2[2 * i + 1], 0.5f * v.z, 0.5f * v.w);
            }
        }

        hA[j] = hidden0[(long)b * NH + j];
        float* row = out + (long)b * TT * NH + j;

        BAR_CONS();   // hA visible to all consumer threads

        #pragma unroll 1
        for (int tb = 0; tb < N_TILES; tb++) {
            while (ld_acquire_shared(&flags[0]) < tb + 1) __nanosleep(64);

            #pragma unroll 1
            for (int tt = 0; tt < TILE_T; tt += 2) {
                const int t = tb * TILE_T + tt;
                SCAN_STEP(hA, hB, t)
                SCAN_STEP(hB, hA, t + 1)
            }
            if (j == 0) st_release_shared(&flags[1], tb + 1);
        }
    }
}

// ======================================================================
extern "C" void kernel_launch(void* const* d_in, const int* in_sizes, int n_in,
                              void* d_out, int out_size)
{
    const float* inp     = (const float*)d_in[0];  // [B,T,NI]
    const float* hidden0 = (const float*)d_in[1];  // [B,NH]
    const float* W_in    = (const float*)d_in[2];  // [NH,NI]
    const float* b_in    = (const float*)d_in[3];  // [NH]
    const float* W_hh    = (const float*)d_in[4];  // [NH,NH]
    const float* b_hh    = (const float*)d_in[5];  // [NH]
    float* out = (float*)d_out;                    // [B,T,NH]

    const int smem_bytes = SMEM_F * 4;   // 230432 B (~225KB)
    cudaFuncSetAttribute(fused_rnn_kernel,
                         cudaFuncAttributeMaxDynamicSharedMemorySize, smem_bytes);

    fused_rnn_kernel<<<BB, 256, smem_bytes>>>(inp, hidden0, W_in, b_in,
                                              W_hh, b_hh, out);
}